// round 12
// baseline (speedup 1.0000x reference)
#include <cuda_runtime.h>
#include <math.h>

#define NTOK   98304
#define CDIM   64
#define KCODES 1024

typedef unsigned long long ull;

// ---- scratch (no allocations allowed; __device__ globals per harness rules) ----
__device__ float g_buf0[(size_t)NTOK * 512];
__device__ float g_buf1[(size_t)NTOK * 512];
__device__ float g_lat [(size_t)NTOK * CDIM];
__device__ float g_dw  [CDIM * KCODES];
__device__ int   g_counts[KCODES];
__device__ float g_enorm [KCODES];
__device__ float g_loss;

__device__ __forceinline__ float gelu_tanh(float x) {
    float x3 = x * x * x;
    return 0.5f * x * (1.0f + tanhf(0.7978845608028654f * (x + 0.044715f * x3)));
}

// Packed dual-fp32 FMA (Blackwell f32x2 pipe; ptxas never emits this from C++)
__device__ __forceinline__ ull fma2(ull a, ull b, ull c) {
    ull d;
    asm("fma.rn.f32x2 %0, %1, %2, %3;" : "=l"(d) : "l"(a), "l"(b), "l"(c));
    return d;
}
__device__ __forceinline__ ull dup2(float x) {
    ull d;
    asm("mov.b64 %0, {%1, %1};" : "=l"(d) : "f"(x));
    return d;
}
__device__ __forceinline__ ull pack2(float lo, float hi) {
    ull d;
    asm("mov.b64 %0, {%1, %2};" : "=l"(d) : "f"(lo), "f"(hi));
    return d;
}
__device__ __forceinline__ void unpack2(ull d, float& lo, float& hi) {
    asm("mov.b64 {%0, %1}, %2;" : "=f"(lo), "=f"(hi) : "l"(d));
}

// Zero accumulators + precompute code norms: sum_c emb[c][j]^2
__global__ void init_kernel(const float* __restrict__ emb) {
    int t = threadIdx.x;  // 1024 threads
    for (int i = t; i < CDIM * KCODES; i += 1024) g_dw[i] = 0.f;
    g_counts[t] = 0;
    if (t == 0) g_loss = 0.f;
    float s = 0.f;
    #pragma unroll
    for (int c = 0; c < CDIM; c++) {
        float v = emb[c * KCODES + t];
        s = fmaf(v, v, s);
    }
    g_enorm[t] = s;
}

// ---- fp32 GEMM + bias + gelu, f32x2-packed, occupancy-optimized ----
// C[N,M] = gelu(A[N,K] @ W[K,M] + b). TM=128, TN=64, TK=8.
// 256 threads in a 32x8 grid, micro-tile 4 rows x 8 cols (4x4 ull acc).
// 3 CTAs/SM (24 warps) to hide LDS latency; fma-bound steady state.
__global__ __launch_bounds__(256, 3) void gemm_bias_gelu(
    const float* __restrict__ A, const float* __restrict__ W,
    const float* __restrict__ bias, float* __restrict__ C,
    int N, int K, int M)
{
    constexpr int TM = 128, TN = 64, TK = 8;
    __shared__ __align__(16) float As[2][TK][TM];
    __shared__ __align__(16) float Bs[2][TK][TN];

    const int tid = threadIdx.x;
    const int bm = blockIdx.y * TM;
    const int bn = blockIdx.x * TN;
    // 32x8 thread grid: 4 rows x 8 cols per thread
    const int mt = (tid >> 3) * 4;
    const int nt = (tid & 7) * 8;

    // A staging: 128 rows x 8 floats = 256 float4, one per thread.
    const int arow = tid >> 1;
    const int acol = (tid & 1) * 4;
    // B staging: 8 x 64 floats = 128 float4, threads 0..127.
    const int brow = (tid < 128) ? (tid >> 4) : 0;
    const int bcol = (tid < 128) ? (tid & 15) * 4 : 0;

    const float* Aptr = A + (size_t)(bm + arow) * K + acol;
    const float* Wptr = W + (size_t)brow * M + bn + bcol;

    ull acc2[4][4];
    #pragma unroll
    for (int i = 0; i < 4; i++)
        #pragma unroll
        for (int j = 0; j < 4; j++) acc2[i][j] = 0ull;  // {+0.f, +0.f}

    // Prologue: tile 0 -> buffer 0
    float4 ar = *reinterpret_cast<const float4*>(Aptr);
    float4 br;
    if (tid < 128) br = *reinterpret_cast<const float4*>(Wptr);
    As[0][acol + 0][arow] = ar.x; As[0][acol + 1][arow] = ar.y;
    As[0][acol + 2][arow] = ar.z; As[0][acol + 3][arow] = ar.w;
    if (tid < 128) *reinterpret_cast<float4*>(&Bs[0][brow][bcol]) = br;
    __syncthreads();

    int buf = 0;
    for (int k0 = 0; k0 < K; k0 += TK) {
        const bool more = (k0 + TK) < K;
        if (more) {
            ar = *reinterpret_cast<const float4*>(Aptr + k0 + TK);
            if (tid < 128)
                br = *reinterpret_cast<const float4*>(Wptr + (size_t)(k0 + TK) * M);
        }

        #pragma unroll
        for (int kk = 0; kk < TK; kk++) {
            // A fragment: 4 scalars (1x LDS.128)
            float4 a0 = *reinterpret_cast<const float4*>(&As[buf][kk][mt]);
            float a[4] = {a0.x, a0.y, a0.z, a0.w};
            // B fragment: 8 consecutive floats = 4 packed pairs (2x LDS.128)
            ull b2[4];
            {
                ulonglong2 t0 = *reinterpret_cast<const ulonglong2*>(&Bs[buf][kk][nt]);
                ulonglong2 t1 = *reinterpret_cast<const ulonglong2*>(&Bs[buf][kk][nt + 4]);
                b2[0] = t0.x; b2[1] = t0.y; b2[2] = t1.x; b2[3] = t1.y;
            }
            #pragma unroll
            for (int i = 0; i < 4; i++) {
                ull ad = dup2(a[i]);
                #pragma unroll
                for (int j = 0; j < 4; j++)
                    acc2[i][j] = fma2(ad, b2[j], acc2[i][j]);
            }
        }

        if (more) {
            int nb = buf ^ 1;
            As[nb][acol + 0][arow] = ar.x; As[nb][acol + 1][arow] = ar.y;
            As[nb][acol + 2][arow] = ar.z; As[nb][acol + 3][arow] = ar.w;
            if (tid < 128) *reinterpret_cast<float4*>(&Bs[nb][brow][bcol]) = br;
        }
        __syncthreads();
        buf ^= 1;
    }

    // Epilogue: unpack pairs, bias + gelu, vectorized store
    float bv[8];
    #pragma unroll
    for (int j = 0; j < 8; j++) bv[j] = bias[bn + nt + j];
    #pragma unroll
    for (int i = 0; i < 4; i++) {
        float o[8];
        #pragma unroll
        for (int j = 0; j < 4; j++) {
            float lo, hi;
            unpack2(acc2[i][j], lo, hi);
            o[2 * j]     = gelu_tanh(lo + bv[2 * j]);
            o[2 * j + 1] = gelu_tanh(hi + bv[2 * j + 1]);
        }
        float* crow = C + (size_t)(bm + mt + i) * M + bn + nt;
        *reinterpret_cast<float4*>(crow)     = make_float4(o[0], o[1], o[2], o[3]);
        *reinterpret_cast<float4*>(crow + 4) = make_float4(o[4], o[5], o[6], o[7]);
    }
}

// ---- VQ: per-token argmin over 1024 codes (f32x2 dot), scatter stats ----
__global__ __launch_bounds__(256) void vq_kernel(
    const float* __restrict__ latent, const float* __restrict__ emb,
    float* __restrict__ out_q, float* __restrict__ out_idx)
{
    __shared__ __align__(16) float se[64][68];
    __shared__ float sn[64];
    __shared__ float wsum[8];

    const int tok = blockIdx.x * 256 + threadIdx.x;
    ull f2[32];
    #pragma unroll
    for (int c = 0; c < 64; c += 4) {
        float4 v = *reinterpret_cast<const float4*>(latent + (size_t)tok * 64 + c);
        f2[c / 2]     = pack2(v.x, v.y);
        f2[c / 2 + 1] = pack2(v.z, v.w);
    }

    float best = -3.4e38f;
    int bestj = 0;
    for (int ch = 0; ch < KCODES; ch += 64) {
        #pragma unroll
        for (int r = 0; r < 16; r++) {
            int e = threadIdx.x + r * 256;
            int c = e >> 6, j = e & 63;
            se[j][c] = emb[c * KCODES + ch + j];
        }
        if (threadIdx.x < 64) sn[threadIdx.x] = g_enorm[ch + threadIdx.x];
        __syncthreads();

        #pragma unroll 2
        for (int j = 0; j < 64; j++) {
            const ulonglong2* row = reinterpret_cast<const ulonglong2*>(&se[j][0]);
            ull d = 0ull;
            #pragma unroll
            for (int cc = 0; cc < 16; cc++) {
                ulonglong2 v = row[cc];
                d = fma2(f2[2 * cc],     v.x, d);
                d = fma2(f2[2 * cc + 1], v.y, d);
            }
            float lo, hi;
            unpack2(d, lo, hi);
            float score = 2.f * (lo + hi) - sn[j];
            if (score > best) { best = score; bestj = ch + j; }
        }
        __syncthreads();
    }

    out_idx[tok] = (float)bestj;

    float lsum = 0.f;
    #pragma unroll
    for (int c2 = 0; c2 < 32; c2++) {
        float x0, x1;
        unpack2(f2[c2], x0, x1);
        float q0 = __ldg(&emb[(2 * c2)     * KCODES + bestj]);
        float q1 = __ldg(&emb[(2 * c2 + 1) * KCODES + bestj]);
        out_q[(size_t)tok * 64 + 2 * c2]     = q0;
        out_q[(size_t)tok * 64 + 2 * c2 + 1] = q1;
        float d0 = q0 - x0, d1 = q1 - x1;
        lsum = fmaf(d0, d0, lsum);
        lsum = fmaf(d1, d1, lsum);
        atomicAdd(&g_dw[(2 * c2)     * KCODES + bestj], x0);
        atomicAdd(&g_dw[(2 * c2 + 1) * KCODES + bestj], x1);
    }
    atomicAdd(&g_counts[bestj], 1);

    #pragma unroll
    for (int o = 16; o > 0; o >>= 1)
        lsum += __shfl_down_sync(0xffffffffu, lsum, o);
    int lane = threadIdx.x & 31, w = threadIdx.x >> 5;
    if (lane == 0) wsum[w] = lsum;
    __syncthreads();
    if (threadIdx.x == 0) {
        float s = 0.f;
        #pragma unroll
        for (int i = 0; i < 8; i++) s += wsum[i];
        atomicAdd(&g_loss, s);
    }
}

// ---- EMA finalize: loss, perplexity, new_embeddings ----
__global__ void finalize_kernel(
    const float* __restrict__ ema_cluster, const float* __restrict__ ema_dw,
    float* __restrict__ out_loss, float* __restrict__ out_perp,
    float* __restrict__ out_emb)
{
    __shared__ float red[1024];
    int j = threadIdx.x;
    const float debias = (float)(1.0 - pow(0.99, 1001.0));

    float cnt = (float)g_counts[j];
    float cs = (ema_cluster[j] * 0.99f + cnt * 0.01f) / debias;

    red[j] = cs;
    __syncthreads();
    for (int s = 512; s > 0; s >>= 1) {
        if (j < s) red[j] += red[j + s];
        __syncthreads();
    }
    float n = red[0];
    __syncthreads();

    float stable = (cs + 1e-5f) / (n + 1024.f * 1e-5f) * n;
    for (int c = 0; c < 64; c++) {
        int idx = c * 1024 + j;
        float upd = (ema_dw[idx] * 0.99f + g_dw[idx] * 0.01f) / debias;
        out_emb[idx] = upd / stable;
    }

    float ap = cnt / (float)NTOK;
    red[j] = ap * logf(ap + 1e-10f);
    __syncthreads();
    for (int s = 512; s > 0; s >>= 1) {
        if (j < s) red[j] += red[j + s];
        __syncthreads();
    }
    if (j == 0) {
        out_perp[0] = expf(-red[0]);
        out_loss[0] = 0.25f * (g_loss / (float)((size_t)NTOK * CDIM));
    }
}

extern "C" void kernel_launch(void* const* d_in, const int* in_sizes, int n_in,
                              void* d_out, int out_size)
{
    const float* states      = (const float*)d_in[0];
    const float* w_se        = (const float*)d_in[1];
    const float* b_se        = (const float*)d_in[2];
    const float* w0          = (const float*)d_in[3];
    const float* b0          = (const float*)d_in[4];
    const float* w1          = (const float*)d_in[5];
    const float* b1          = (const float*)d_in[6];
    const float* w2          = (const float*)d_in[7];
    const float* b2          = (const float*)d_in[8];
    const float* emb         = (const float*)d_in[9];
    const float* ema_cluster = (const float*)d_in[10];
    const float* ema_dw      = (const float*)d_in[11];
    float* out = (float*)d_out;

    float *buf0, *buf1, *lat;
    cudaGetSymbolAddress((void**)&buf0, g_buf0);
    cudaGetSymbolAddress((void**)&buf1, g_buf1);
    cudaGetSymbolAddress((void**)&lat,  g_lat);

    float* out_q    = out;
    float* out_loss = out + 6291456;
    float* out_perp = out + 6291457;
    float* out_idx  = out + 6291458;
    float* out_emb  = out + 6389762;

    init_kernel<<<1, 1024>>>(emb);

    gemm_bias_gelu<<<dim3(8, NTOK / 128), 256>>>(states, w_se, b_se, buf0, NTOK, 256, 512);
    gemm_bias_gelu<<<dim3(8, NTOK / 128), 256>>>(buf0,   w0,   b0,   buf1, NTOK, 512, 512);
    gemm_bias_gelu<<<dim3(8, NTOK / 128), 256>>>(buf1,   w1,   b1,   buf0, NTOK, 512, 512);
    gemm_bias_gelu<<<dim3(1, NTOK / 128), 256>>>(buf0,   w2,   b2,   lat,  NTOK, 512, 64);

    vq_kernel<<<NTOK / 256, 256>>>(lat, emb, out_q, out_idx);

    finalize_kernel<<<1, 1024>>>(ema_cluster, ema_dw, out_loss, out_perp, out_emb);
}